// round 1
// baseline (speedup 1.0000x reference)
#include <cuda_runtime.h>

// UnifiedQuantumRegressor — algebraically reduced:
//   mean_w == 1.0 identically (wsum == deg elementwise), so the entire
//   pairwise-fidelity Gram matrix is dead code. Output is
//   out = (sum_n tanh(relu(relu(X@W1+b1)@W2+b2)@Wq+bq)) @ Wh + bh  (scalar)
//
// Fully fused per 64-row block: GEMM1 -> relu -> GEMM2 -> relu -> GEMM3 ->
// tanh -> row-sum, all intermediates in SMEM. fp32 throughout, inner loops
// use packed fma.rn.f32x2 (SASS FFMA2) for 2x fp32 FMA throughput.

#define N_ROWS 8192
#define F_IN   512
#define HID    256
#define WDIM   64
#define BM     64
#define BK     32
#define AS_STR 65      // padded transpose-tile stride
#define ENC_STR 264    // padded enc stride (rows land on distinct banks)
#define NBLK   (N_ROWS / BM)   // 128 CTAs

#define SMEM_FLOATS (BK*AS_STR + BK*HID + BM*ENC_STR)
#define SMEM_BYTES  (SMEM_FLOATS * 4)

typedef unsigned long long ull;

__device__ float g_part[NBLK * WDIM];

__device__ __forceinline__ ull pack2(float x, float y) {
    ull r;
    asm("mov.b64 %0, {%1,%2};" : "=l"(r) : "f"(x), "f"(y));
    return r;
}
__device__ __forceinline__ void unpack2(ull v, float& x, float& y) {
    asm("mov.b64 {%0,%1}, %2;" : "=f"(x), "=f"(y) : "l"(v));
}
__device__ __forceinline__ void ffma2(ull& d, ull a, ull b) {
    asm("fma.rn.f32x2 %0, %1, %2, %0;" : "+l"(d) : "l"(a), "l"(b));
}

extern "C" __global__ void __launch_bounds__(256, 1)
uqr_fused_kernel(const float* __restrict__ X,  const float* __restrict__ W1,
                 const float* __restrict__ b1, const float* __restrict__ W2,
                 const float* __restrict__ b2, const float* __restrict__ Wq,
                 const float* __restrict__ bq)
{
    extern __shared__ float smem[];
    float* As  = smem;                 // [BK][AS_STR]  (X tile, transposed)
    float* Bs  = As + BK * AS_STR;     // [BK][HID]     (weight tile)
    float* Enc = Bs + BK * HID;        // [BM][ENC_STR] (activations)

    const int tid = threadIdx.x;
    const int tx  = tid & 15;          // 16 col-groups
    const int ty  = tid >> 4;          // 16 row-groups
    const int m0  = blockIdx.x * BM;
    const int r0  = ty * 4;            // 4 rows per thread

    // 4 rows x 8 f32x2 col-pairs = 4x16 fp32 outputs per thread
    ull acc[4][8];
#pragma unroll
    for (int i = 0; i < 4; ++i)
#pragma unroll
        for (int j = 0; j < 8; ++j) acc[i][j] = 0ULL;

    // ---------------- Phase 1: enc1 = relu(X @ W1 + b1) ----------------
    const float* Xb = X + (size_t)m0 * F_IN;
    for (int kb = 0; kb < F_IN; kb += BK) {
        // stage X tile transposed: As[k][row]
#pragma unroll
        for (int it = 0; it < 2; ++it) {
            int t  = tid + it * 256;
            int r  = t >> 3;
            int kq = (t & 7) << 2;
            float4 v = *(const float4*)(Xb + (size_t)r * F_IN + kb + kq);
            As[(kq + 0) * AS_STR + r] = v.x;
            As[(kq + 1) * AS_STR + r] = v.y;
            As[(kq + 2) * AS_STR + r] = v.z;
            As[(kq + 3) * AS_STR + r] = v.w;
        }
        // stage W1 tile: Bs[k][c]
#pragma unroll
        for (int it = 0; it < 8; ++it) {
            int t  = tid + it * 256;
            int k  = t >> 6;
            int cq = (t & 63) << 2;
            *(float4*)(Bs + k * HID + cq) =
                *(const float4*)(W1 + (size_t)(kb + k) * HID + cq);
        }
        __syncthreads();
#pragma unroll 4
        for (int k = 0; k < BK; ++k) {
            ull a2[4];
#pragma unroll
            for (int i = 0; i < 4; ++i) {
                float a = As[k * AS_STR + r0 + i];
                a2[i] = pack2(a, a);
            }
#pragma unroll
            for (int j = 0; j < 8; ++j) {
                ull b2 = *(const ull*)(Bs + k * HID + 2 * tx + 32 * j);
#pragma unroll
                for (int i = 0; i < 4; ++i) ffma2(acc[i][j], a2[i], b2);
            }
        }
        __syncthreads();
    }
    // epilogue 1: bias + relu -> Enc
#pragma unroll
    for (int j = 0; j < 8; ++j) {
        int c = 2 * tx + 32 * j;
        float bx = b1[c], by = b1[c + 1];
#pragma unroll
        for (int i = 0; i < 4; ++i) {
            float x, y;
            unpack2(acc[i][j], x, y);
            x = fmaxf(x + bx, 0.f);
            y = fmaxf(y + by, 0.f);
            Enc[(r0 + i) * ENC_STR + c]     = x;
            Enc[(r0 + i) * ENC_STR + c + 1] = y;
            acc[i][j] = 0ULL;
        }
    }
    __syncthreads();

    // ---------------- Phase 2: enc2 = relu(enc1 @ W2 + b2) ----------------
    for (int kb = 0; kb < HID; kb += BK) {
#pragma unroll
        for (int it = 0; it < 8; ++it) {
            int t  = tid + it * 256;
            int k  = t >> 6;
            int cq = (t & 63) << 2;
            *(float4*)(Bs + k * HID + cq) =
                *(const float4*)(W2 + (size_t)(kb + k) * HID + cq);
        }
        __syncthreads();
#pragma unroll 4
        for (int k = 0; k < BK; ++k) {
            ull a2[4];
#pragma unroll
            for (int i = 0; i < 4; ++i) {
                float a = Enc[(r0 + i) * ENC_STR + kb + k];
                a2[i] = pack2(a, a);
            }
#pragma unroll
            for (int j = 0; j < 8; ++j) {
                ull b2 = *(const ull*)(Bs + k * HID + 2 * tx + 32 * j);
#pragma unroll
                for (int i = 0; i < 4; ++i) ffma2(acc[i][j], a2[i], b2);
            }
        }
        __syncthreads();
    }
    // epilogue 2: bias + relu -> Enc (all reads done: loop ended with a sync)
#pragma unroll
    for (int j = 0; j < 8; ++j) {
        int c = 2 * tx + 32 * j;
        float bx = b2[c], by = b2[c + 1];
#pragma unroll
        for (int i = 0; i < 4; ++i) {
            float x, y;
            unpack2(acc[i][j], x, y);
            x = fmaxf(x + bx, 0.f);
            y = fmaxf(y + by, 0.f);
            Enc[(r0 + i) * ENC_STR + c]     = x;
            Enc[(r0 + i) * ENC_STR + c + 1] = y;
            acc[i][j] = 0ULL;
        }
    }
    __syncthreads();

    // ---------------- Phase 3: q = tanh(enc2 @ Wq + bq); partial col-sums ----
    for (int kb = 0; kb < HID; kb += BK) {
#pragma unroll
        for (int it = 0; it < 2; ++it) {
            int t  = tid + it * 256;
            int k  = t >> 4;
            int cq = (t & 15) << 2;
            *(float4*)(Bs + k * WDIM + cq) =
                *(const float4*)(Wq + (size_t)(kb + k) * WDIM + cq);
        }
        __syncthreads();
#pragma unroll 4
        for (int k = 0; k < BK; ++k) {
            ull a2[4];
#pragma unroll
            for (int i = 0; i < 4; ++i) {
                float a = Enc[(r0 + i) * ENC_STR + kb + k];
                a2[i] = pack2(a, a);
            }
#pragma unroll
            for (int j = 0; j < 2; ++j) {
                ull b2 = *(const ull*)(Bs + k * WDIM + 2 * tx + 32 * j);
#pragma unroll
                for (int i = 0; i < 4; ++i) ffma2(acc[i][j], a2[i], b2);
            }
        }
        __syncthreads();
    }

    // epilogue 3: bias + tanh + per-thread row-sum -> per-CTA column partials
    float* Red = As;   // reuse: [16][64]
#pragma unroll
    for (int j = 0; j < 2; ++j) {
        int c = 2 * tx + 32 * j;
        float bx = bq[c], by = bq[c + 1];
        float sx = 0.f, sy = 0.f;
#pragma unroll
        for (int i = 0; i < 4; ++i) {
            float x, y;
            unpack2(acc[i][j], x, y);
            sx += tanhf(x + bx);
            sy += tanhf(y + by);
        }
        Red[ty * 64 + c]     = sx;
        Red[ty * 64 + c + 1] = sy;
    }
    __syncthreads();
    if (tid < WDIM) {
        float s = 0.f;
#pragma unroll
        for (int t2 = 0; t2 < 16; ++t2) s += Red[t2 * 64 + tid];
        g_part[blockIdx.x * WDIM + tid] = s;   // deterministic: no atomics
    }
}

extern "C" __global__ void uqr_finalize_kernel(const float* __restrict__ Wh,
                                               const float* __restrict__ bh,
                                               float* __restrict__ out)
{
    __shared__ float sm[WDIM];
    int c = threadIdx.x;   // 64 threads
    float s = 0.f;
    for (int b = 0; b < NBLK; ++b) s += g_part[b * WDIM + c];
    sm[c] = s * Wh[c];
    __syncthreads();
    if (c == 0) {
        float t = 0.f;
#pragma unroll
        for (int i = 0; i < WDIM; ++i) t += sm[i];
        out[0] = t + bh[0];
    }
}

extern "C" void kernel_launch(void* const* d_in, const int* in_sizes, int n_in,
                              void* d_out, int out_size)
{
    const float* X  = (const float*)d_in[0];
    const float* W1 = (const float*)d_in[1];
    const float* b1 = (const float*)d_in[2];
    const float* W2 = (const float*)d_in[3];
    const float* b2 = (const float*)d_in[4];
    const float* Wq = (const float*)d_in[5];
    const float* bq = (const float*)d_in[6];
    const float* Wh = (const float*)d_in[7];
    const float* bh = (const float*)d_in[8];
    float* out = (float*)d_out;

    cudaFuncSetAttribute(uqr_fused_kernel,
                         cudaFuncAttributeMaxDynamicSharedMemorySize, SMEM_BYTES);
    uqr_fused_kernel<<<NBLK, 256, SMEM_BYTES>>>(X, W1, b1, W2, b2, Wq, bq);
    uqr_finalize_kernel<<<1, WDIM>>>(Wh, bh, out);
}

// round 5
// speedup vs baseline: 1.4175x; 1.4175x over previous
#include <cuda_runtime.h>
#include <cuda_bf16.h>

#define N_ROWS  8192
#define F_IN    512
#define HID     256
#define WDIM    64
#define BM      64
#define NBLK    (N_ROWS / BM)     // 128 CTAs
#define THREADS 256

// ---- SMEM layout (byte offsets). Strides are odd multiples of 16B so all
// ldmatrix row addresses hit distinct 16B phases (conflict-free). ----
#define ASTRB   144               // A tile row stride: 72 bf16
#define BSTRB   144               // B tile row stride: 72 bf16
#define ESTRB   528               // Enc row stride: 264 bf16
#define OFF_AS_HI  0
#define OFF_AS_LO  9216
#define OFF_BS_HI  18432
#define OFF_BS_LO  55296
#define OFF_ENC_HI 92160
#define OFF_ENC_LO 125952
#define OFF_RED    159744
#define SMEM_TOTAL 159808

// ---- device scratch: weights transposed [n][k] + bf16 hi/lo split ----
__device__ __align__(16) __nv_bfloat16 g_W1t_hi[HID * F_IN];
__device__ __align__(16) __nv_bfloat16 g_W1t_lo[HID * F_IN];
__device__ __align__(16) __nv_bfloat16 g_W2t_hi[HID * HID];
__device__ __align__(16) __nv_bfloat16 g_W2t_lo[HID * HID];
__device__ __align__(16) __nv_bfloat16 g_Wqt_hi[WDIM * HID];
__device__ __align__(16) __nv_bfloat16 g_Wqt_lo[WDIM * HID];
__device__ float        g_part[NBLK];
__device__ unsigned int g_cnt = 0;

// ---- helpers ----
__device__ __forceinline__ unsigned smem_u32(const void* p) {
    unsigned a;
    asm("{ .reg .u64 t; cvta.to.shared.u64 t, %1; cvt.u32.u64 %0, t; }" : "=r"(a) : "l"(p));
    return a;
}
__device__ __forceinline__ void ldsm_x4(unsigned addr, unsigned r[4]) {
    asm volatile("ldmatrix.sync.aligned.m8n8.x4.shared.b16 {%0,%1,%2,%3}, [%4];"
                 : "=r"(r[0]), "=r"(r[1]), "=r"(r[2]), "=r"(r[3]) : "r"(addr));
}
__device__ __forceinline__ void mma16816(float d[4], const unsigned a[4],
                                         unsigned b0, unsigned b1) {
    asm volatile(
        "mma.sync.aligned.m16n8k16.row.col.f32.bf16.bf16.f32 "
        "{%0,%1,%2,%3}, {%4,%5,%6,%7}, {%8,%9}, {%0,%1,%2,%3};"
        : "+f"(d[0]), "+f"(d[1]), "+f"(d[2]), "+f"(d[3])
        : "r"(a[0]), "r"(a[1]), "r"(a[2]), "r"(a[3]), "r"(b0), "r"(b1));
}
__device__ __forceinline__ void split_pack2(float x, float y, unsigned& hi2, unsigned& lo2) {
    __nv_bfloat16 hx = __float2bfloat16(x);
    __nv_bfloat16 hy = __float2bfloat16(y);
    float rx = x - __bfloat162float(hx);
    float ry = y - __bfloat162float(hy);
    __nv_bfloat162 h; h.x = hx; h.y = hy;
    __nv_bfloat162 l; l.x = __float2bfloat16(rx); l.y = __float2bfloat16(ry);
    hi2 = *reinterpret_cast<unsigned*>(&h);
    lo2 = *reinterpret_cast<unsigned*>(&l);
}

// ---- prep: transpose + bf16 hi/lo split of weights (runs once per launch) --
extern "C" __global__ void uqr_prep(const float* __restrict__ W1,
                                    const float* __restrict__ W2,
                                    const float* __restrict__ Wq)
{
    int idx = blockIdx.x * blockDim.x + threadIdx.x;
    float v; __nv_bfloat16 *ph, *pl; int o;
    if (idx < HID * F_IN) {
        int n = idx / F_IN, k = idx - n * F_IN;
        v = W1[k * HID + n]; ph = g_W1t_hi; pl = g_W1t_lo; o = idx;
    } else if (idx < HID * F_IN + HID * HID) {
        int j = idx - HID * F_IN;
        int n = j / HID, k = j - n * HID;
        v = W2[k * HID + n]; ph = g_W2t_hi; pl = g_W2t_lo; o = j;
    } else if (idx < HID * F_IN + HID * HID + WDIM * HID) {
        int j = idx - HID * F_IN - HID * HID;
        int n = j / HID, k = j - n * HID;
        v = Wq[k * WDIM + n]; ph = g_Wqt_hi; pl = g_Wqt_lo; o = j;
    } else return;
    __nv_bfloat16 h = __float2bfloat16(v);
    ph[o] = h;
    pl[o] = __float2bfloat16(v - __bfloat162float(h));
}

// ---- one K=64 chunk of 3-term split GEMM for one warp ----
// NT = n8-tiles per warp (8 for N=256 warp-tile 32x64; 2 for N=64 warp-tile 32x16)
// B is stored [n][k] row-major => non-trans ldmatrix gives the col-major k x n
// fragment mma.row.col expects (consecutive k at fixed n per lane).
template<int NT>
__device__ __forceinline__ void gemm_chunk(
    unsigned aHi, unsigned aLo, int aStrB, int aK0,
    unsigned bHi, unsigned bLo,
    int wm, int wnoff, int lane, float acc[2 * NT][4])
{
#pragma unroll
    for (int ks = 0; ks < 4; ++ks) {
        const int kA = aK0 + ks * 16;
        const int kB = ks * 16;
        const int arow = wm * 32 + (lane & 15);
        const int acol = kA + ((lane >> 4) << 3);
        unsigned a0h[4], a1h[4], a0l[4], a1l[4];
        {
            unsigned aAddrH = aHi + (unsigned)(arow * aStrB + acol * 2);
            unsigned aAddrL = aLo + (unsigned)(arow * aStrB + acol * 2);
            ldsm_x4(aAddrH, a0h);
            ldsm_x4(aAddrH + 16 * aStrB, a1h);
            ldsm_x4(aAddrL, a0l);
            ldsm_x4(aAddrL + 16 * aStrB, a1l);
        }
#pragma unroll
        for (int p = 0; p < NT / 2; ++p) {
            // lanes 0-7: n rows 0-7 @k0 (b0, tile p.0); 8-15: same rows @k+8 (b1);
            // 16-23: n rows 8-15 @k0; 24-31: @k+8
            const int brow = wnoff + p * 16 + (lane & 7) + ((lane & 16) ? 8 : 0);
            const int bcol = kB + ((lane & 8) ? 8 : 0);
            unsigned bh[4], bl[4];
            ldsm_x4(bHi + (unsigned)(brow * BSTRB + bcol * 2), bh);
            ldsm_x4(bLo + (unsigned)(brow * BSTRB + bcol * 2), bl);
            // term Ah*Bh
            mma16816(acc[0 * NT + 2 * p],     a0h, bh[0], bh[1]);
            mma16816(acc[0 * NT + 2 * p + 1], a0h, bh[2], bh[3]);
            mma16816(acc[1 * NT + 2 * p],     a1h, bh[0], bh[1]);
            mma16816(acc[1 * NT + 2 * p + 1], a1h, bh[2], bh[3]);
            // term Ah*Bl
            mma16816(acc[0 * NT + 2 * p],     a0h, bl[0], bl[1]);
            mma16816(acc[0 * NT + 2 * p + 1], a0h, bl[2], bl[3]);
            mma16816(acc[1 * NT + 2 * p],     a1h, bl[0], bl[1]);
            mma16816(acc[1 * NT + 2 * p + 1], a1h, bl[2], bl[3]);
            // term Al*Bh
            mma16816(acc[0 * NT + 2 * p],     a0l, bh[0], bh[1]);
            mma16816(acc[0 * NT + 2 * p + 1], a0l, bh[2], bh[3]);
            mma16816(acc[1 * NT + 2 * p],     a1l, bh[0], bh[1]);
            mma16816(acc[1 * NT + 2 * p + 1], a1l, bh[2], bh[3]);
        }
    }
}

// stage a 64-wide K chunk of a pre-split transposed weight matrix into Bs
__device__ __forceinline__ void stage_w(char* smem, const __nv_bfloat16* wh,
                                        const __nv_bfloat16* wl, int wstr, int kb, int tid)
{
    const int n = tid;
    const uint4* sh = (const uint4*)(wh + (size_t)n * wstr + kb);
    const uint4* sl = (const uint4*)(wl + (size_t)n * wstr + kb);
    uint4* dh = (uint4*)(smem + OFF_BS_HI + n * BSTRB);
    uint4* dl = (uint4*)(smem + OFF_BS_LO + n * BSTRB);
#pragma unroll
    for (int j = 0; j < 8; ++j) { dh[j] = sh[j]; dl[j] = sl[j]; }
}

// epilogue for GEMM1/2: bias + relu + split -> Enc
template<int NT>
__device__ __forceinline__ void epi_relu(float acc[2 * NT][4], const float* __restrict__ bias,
                                         char* smem, int wm, int wnoff, int lane)
{
#pragma unroll
    for (int mi = 0; mi < 2; ++mi)
#pragma unroll
        for (int nj = 0; nj < NT; ++nj) {
            const int r = wm * 32 + mi * 16 + (lane >> 2);
            const int c = wnoff + nj * 8 + 2 * (lane & 3);
            const float bx = bias[c], by = bias[c + 1];
            float* a = acc[mi * NT + nj];
            float x0 = fmaxf(a[0] + bx, 0.f), y0 = fmaxf(a[1] + by, 0.f);
            float x1 = fmaxf(a[2] + bx, 0.f), y1 = fmaxf(a[3] + by, 0.f);
            unsigned h0, l0, h1, l1;
            split_pack2(x0, y0, h0, l0);
            split_pack2(x1, y1, h1, l1);
            *(unsigned*)(smem + OFF_ENC_HI + r * ESTRB + c * 2)       = h0;
            *(unsigned*)(smem + OFF_ENC_LO + r * ESTRB + c * 2)       = l0;
            *(unsigned*)(smem + OFF_ENC_HI + (r + 8) * ESTRB + c * 2) = h1;
            *(unsigned*)(smem + OFF_ENC_LO + (r + 8) * ESTRB + c * 2) = l1;
            a[0] = a[1] = a[2] = a[3] = 0.f;
        }
}

// ---- main fused kernel ----
extern "C" __global__ void __launch_bounds__(THREADS, 1)
uqr_main(const float* __restrict__ X,  const float* __restrict__ b1p,
         const float* __restrict__ b2p, const float* __restrict__ bqp,
         const float* __restrict__ Whp, const float* __restrict__ bhp,
         float* __restrict__ out)
{
    extern __shared__ char smem[];
    const unsigned sb = smem_u32(smem);
    const int tid  = threadIdx.x;
    const int lane = tid & 31;
    const int wid  = tid >> 5;
    const int wm   = wid & 1;          // 2 warp-rows  (32 rows each)
    const int wn   = wid >> 1;         // 4 warp-cols
    const int m0   = blockIdx.x * BM;

    const unsigned aHi1 = sb + OFF_AS_HI,  aLo1 = sb + OFF_AS_LO;
    const unsigned bHi  = sb + OFF_BS_HI,  bLo  = sb + OFF_BS_LO;
    const unsigned eHi  = sb + OFF_ENC_HI, eLo  = sb + OFF_ENC_LO;

    float acc[16][4];
#pragma unroll
    for (int i = 0; i < 16; ++i)
        acc[i][0] = acc[i][1] = acc[i][2] = acc[i][3] = 0.f;

    // ================= GEMM1: enc1 = relu(X @ W1 + b1) =================
    for (int kb = 0; kb < F_IN; kb += 64) {
        if (kb) __syncthreads();           // previous chunk compute done
        // stage X chunk: fp32 -> bf16 hi/lo split
        {
            const int row = tid >> 2;
            const int kq  = (tid & 3) << 4;
            const float4* src = (const float4*)(X + (size_t)(m0 + row) * F_IN + kb + kq);
            float4 v0 = src[0], v1 = src[1], v2 = src[2], v3 = src[3];
            unsigned h[8], l[8];
            split_pack2(v0.x, v0.y, h[0], l[0]); split_pack2(v0.z, v0.w, h[1], l[1]);
            split_pack2(v1.x, v1.y, h[2], l[2]); split_pack2(v1.z, v1.w, h[3], l[3]);
            split_pack2(v2.x, v2.y, h[4], l[4]); split_pack2(v2.z, v2.w, h[5], l[5]);
            split_pack2(v3.x, v3.y, h[6], l[6]); split_pack2(v3.z, v3.w, h[7], l[7]);
            uint4* dh = (uint4*)(smem + OFF_AS_HI + row * ASTRB + kq * 2);
            uint4* dl = (uint4*)(smem + OFF_AS_LO + row * ASTRB + kq * 2);
            dh[0] = make_uint4(h[0], h[1], h[2], h[3]);
            dh[1] = make_uint4(h[4], h[5], h[6], h[7]);
            dl[0] = make_uint4(l[0], l[1], l[2], l[3]);
            dl[1] = make_uint4(l[4], l[5], l[6], l[7]);
        }
        stage_w(smem, g_W1t_hi, g_W1t_lo, F_IN, kb, tid);
        __syncthreads();
        gemm_chunk<8>(aHi1, aLo1, ASTRB, 0, bHi, bLo, wm, wn * 64, lane, acc);
    }
    __syncthreads();
    epi_relu<8>(acc, b1p, smem, wm, wn * 64, lane);

    // ================= GEMM2: enc2 = relu(enc1 @ W2 + b2) ===============
    for (int kb = 0; kb < HID; kb += 64) {
        __syncthreads();                  // Enc writes visible / Bs free
        stage_w(smem, g_W2t_hi, g_W2t_lo, HID, kb, tid);
        __syncthreads();
        gemm_chunk<8>(eHi, eLo, ESTRB, kb, bHi, bLo, wm, wn * 64, lane, acc);
    }
    __syncthreads();                      // all warps done reading Enc
    epi_relu<8>(acc, b2p, smem, wm, wn * 64, lane);

    // ================= GEMM3: z3 = enc2 @ Wq + bq (N=64) ================
    for (int kb = 0; kb < HID; kb += 64) {
        __syncthreads();
        {   // stage Wq chunk: 64 rows x 64 bf16 per split
            const int n  = tid & 63;
            const int j2 = tid >> 6;     // 0..3, 32B each
            const uint4* sh = (const uint4*)(g_Wqt_hi + (size_t)n * HID + kb + j2 * 16);
            const uint4* sl = (const uint4*)(g_Wqt_lo + (size_t)n * HID + kb + j2 * 16);
            uint4* dh = (uint4*)(smem + OFF_BS_HI + n * BSTRB + j2 * 32);
            uint4* dl = (uint4*)(smem + OFF_BS_LO + n * BSTRB + j2 * 32);
            dh[0] = sh[0]; dh[1] = sh[1];
            dl[0] = sl[0]; dl[1] = sl[1];
        }
        __syncthreads();
        gemm_chunk<2>(eHi, eLo, ESTRB, kb, bHi, bLo, wm, wn * 16, lane, acc);
    }

    // ===== epilogue 3: tanh + dot(Wh), deterministic reduction =====
    float s = 0.f;
#pragma unroll
    for (int mi = 0; mi < 2; ++mi)
#pragma unroll
        for (int nj = 0; nj < 2; ++nj) {
            const int c = wn * 16 + nj * 8 + 2 * (lane & 3);
            const float bx = bqp[c], by = bqp[c + 1];
            const float wx = Whp[c], wy = Whp[c + 1];
            float* a = acc[mi * 2 + nj];
            s += tanhf(a[0] + bx) * wx + tanhf(a[1] + by) * wy;
            s += tanhf(a[2] + bx) * wx + tanhf(a[3] + by) * wy;
        }
#pragma unroll
    for (int o = 16; o; o >>= 1) s += __shfl_xor_sync(0xffffffffu, s, o);
    float* red = (float*)(smem + OFF_RED);
    if (lane == 0) red[wid] = s;
    __syncthreads();

    if (tid == 0) {
        float t = 0.f;
#pragma unroll
        for (int w = 0; w < 8; ++w) t += red[w];
        g_part[blockIdx.x] = t;
        __threadfence();
        unsigned old = atomicAdd(&g_cnt, 1);
        if (old == NBLK - 1) {            // last CTA: deterministic serial sum
            __threadfence();
            float acc2 = bhp[0];
#pragma unroll 8
            for (int i = 0; i < NBLK; ++i) acc2 += ((volatile float*)g_part)[i];
            out[0] = acc2;
            *((volatile unsigned*)&g_cnt) = 0;   // reset for next replay
        }
    }
}

extern "C" void kernel_launch(void* const* d_in, const int* in_sizes, int n_in,
                              void* d_out, int out_size)
{
    const float* X  = (const float*)d_in[0];
    const float* W1 = (const float*)d_in[1];
    const float* b1 = (const float*)d_in[2];
    const float* W2 = (const float*)d_in[3];
    const float* b2 = (const float*)d_in[4];
    const float* Wq = (const float*)d_in[5];
    const float* bq = (const float*)d_in[6];
    const float* Wh = (const float*)d_in[7];
    const float* bh = (const float*)d_in[8];
    float* out = (float*)d_out;

    const int prep_elems = HID * F_IN + HID * HID + WDIM * HID;
    uqr_prep<<<(prep_elems + 255) / 256, 256>>>(W1, W2, Wq);

    cudaFuncSetAttribute(uqr_main, cudaFuncAttributeMaxDynamicSharedMemorySize, SMEM_TOTAL);
    uqr_main<<<NBLK, THREADS, SMEM_TOTAL>>>(X, b1, b2, bq, Wh, bh, out);
}

// round 6
// speedup vs baseline: 1.5323x; 1.0810x over previous
#include <cuda_runtime.h>
#include <cuda_bf16.h>

#define N_ROWS  8192
#define F_IN    512
#define HID     256
#define WDIM    64
#define BM      64
#define BK      32
#define NBLK    (N_ROWS / BM)     // 128 CTAs
#define THREADS 256

// ---- SMEM layout. Strides odd multiples of 16B => conflict-free ldmatrix ----
#define ASTRB   80
#define BSTRB   80
#define ESTRB   528
#define OFF_AS_HI  0
#define OFF_AS_LO  5120
#define OFF_B0H    10240
#define OFF_B0L    30720
#define OFF_B1H    51200
#define OFF_B1L    71680
#define OFF_ENC_HI 92160
#define OFF_ENC_LO 125952
#define OFF_RED    159744
#define SMEM_TOTAL 159808

// ---- device scratch: weights transposed [n][k] + bf16 hi/lo split ----
__device__ __align__(16) __nv_bfloat16 g_W1t_hi[HID * F_IN];
__device__ __align__(16) __nv_bfloat16 g_W1t_lo[HID * F_IN];
__device__ __align__(16) __nv_bfloat16 g_W2t_hi[HID * HID];
__device__ __align__(16) __nv_bfloat16 g_W2t_lo[HID * HID];
__device__ __align__(16) __nv_bfloat16 g_Wqt_hi[WDIM * HID];
__device__ __align__(16) __nv_bfloat16 g_Wqt_lo[WDIM * HID];
__device__ float        g_part[NBLK];
__device__ unsigned int g_cnt = 0;

// ---- helpers ----
__device__ __forceinline__ unsigned smem_u32(const void* p) {
    unsigned a;
    asm("{ .reg .u64 t; cvta.to.shared.u64 t, %1; cvt.u32.u64 %0, t; }" : "=r"(a) : "l"(p));
    return a;
}
__device__ __forceinline__ void cp16(unsigned dst, const void* src) {
    asm volatile("cp.async.cg.shared.global [%0], [%1], 16;"
                 :: "r"(dst), "l"(__cvta_generic_to_global(src)) : "memory");
}
#define CP_COMMIT() asm volatile("cp.async.commit_group;" ::: "memory")
#define CP_WAIT0()  asm volatile("cp.async.wait_group 0;" ::: "memory")

__device__ __forceinline__ void ldsm_x4(unsigned addr, unsigned r[4]) {
    asm volatile("ldmatrix.sync.aligned.m8n8.x4.shared.b16 {%0,%1,%2,%3}, [%4];"
                 : "=r"(r[0]), "=r"(r[1]), "=r"(r[2]), "=r"(r[3]) : "r"(addr));
}
__device__ __forceinline__ void mma16816(float d[4], const unsigned a[4],
                                         unsigned b0, unsigned b1) {
    asm volatile(
        "mma.sync.aligned.m16n8k16.row.col.f32.bf16.bf16.f32 "
        "{%0,%1,%2,%3}, {%4,%5,%6,%7}, {%8,%9}, {%0,%1,%2,%3};"
        : "+f"(d[0]), "+f"(d[1]), "+f"(d[2]), "+f"(d[3])
        : "r"(a[0]), "r"(a[1]), "r"(a[2]), "r"(a[3]), "r"(b0), "r"(b1));
}
__device__ __forceinline__ void split_pack2(float x, float y, unsigned& hi2, unsigned& lo2) {
    __nv_bfloat16 hx = __float2bfloat16(x);
    __nv_bfloat16 hy = __float2bfloat16(y);
    float rx = x - __bfloat162float(hx);
    float ry = y - __bfloat162float(hy);
    __nv_bfloat162 h; h.x = hx; h.y = hy;
    __nv_bfloat162 l; l.x = __float2bfloat16(rx); l.y = __float2bfloat16(ry);
    hi2 = *reinterpret_cast<unsigned*>(&h);
    lo2 = *reinterpret_cast<unsigned*>(&l);
}

// ---- prep: transpose + bf16 hi/lo split of weights ----
extern "C" __global__ void uqr_prep(const float* __restrict__ W1,
                                    const float* __restrict__ W2,
                                    const float* __restrict__ Wq)
{
    int idx = blockIdx.x * blockDim.x + threadIdx.x;
    float v; __nv_bfloat16 *ph, *pl; int o;
    if (idx < HID * F_IN) {
        int n = idx / F_IN, k = idx - n * F_IN;
        v = W1[k * HID + n]; ph = g_W1t_hi; pl = g_W1t_lo; o = idx;
    } else if (idx < HID * F_IN + HID * HID) {
        int j = idx - HID * F_IN;
        int n = j / HID, k = j - n * HID;
        v = W2[k * HID + n]; ph = g_W2t_hi; pl = g_W2t_lo; o = j;
    } else if (idx < HID * F_IN + HID * HID + WDIM * HID) {
        int j = idx - HID * F_IN - HID * HID;
        int n = j / HID, k = j - n * HID;
        v = Wq[k * WDIM + n]; ph = g_Wqt_hi; pl = g_Wqt_lo; o = j;
    } else return;
    __nv_bfloat16 h = __float2bfloat16(v);
    ph[o] = h;
    pl[o] = __float2bfloat16(v - __bfloat162float(h));
}

// ---- one BK=32 chunk of 3-term split GEMM for one warp ----
// B stored [n][k] row-major => non-trans ldmatrix = col-major fragment for row.col
template<int NT>
__device__ __forceinline__ void gemm_chunk(
    unsigned aHi, unsigned aLo, int aStrB, int aK0,
    unsigned bHi, unsigned bLo,
    int wm, int wnoff, int lane, float acc[2 * NT][4])
{
#pragma unroll
    for (int ks = 0; ks < 2; ++ks) {
        const int kA = aK0 + ks * 16;
        const int kB = ks * 16;
        const int arow = wm * 32 + (lane & 15);
        const int acol = kA + ((lane >> 4) << 3);
        unsigned a0h[4], a1h[4], a0l[4], a1l[4];
        {
            unsigned aAddrH = aHi + (unsigned)(arow * aStrB + acol * 2);
            unsigned aAddrL = aLo + (unsigned)(arow * aStrB + acol * 2);
            ldsm_x4(aAddrH, a0h);
            ldsm_x4(aAddrH + 16 * aStrB, a1h);
            ldsm_x4(aAddrL, a0l);
            ldsm_x4(aAddrL + 16 * aStrB, a1l);
        }
#pragma unroll
        for (int p = 0; p < NT / 2; ++p) {
            const int brow = wnoff + p * 16 + (lane & 7) + ((lane & 16) ? 8 : 0);
            const int bcol = kB + ((lane & 8) ? 8 : 0);
            unsigned bh[4], bl[4];
            ldsm_x4(bHi + (unsigned)(brow * BSTRB + bcol * 2), bh);
            ldsm_x4(bLo + (unsigned)(brow * BSTRB + bcol * 2), bl);
            mma16816(acc[0 * NT + 2 * p],     a0h, bh[0], bh[1]);
            mma16816(acc[0 * NT + 2 * p + 1], a0h, bh[2], bh[3]);
            mma16816(acc[1 * NT + 2 * p],     a1h, bh[0], bh[1]);
            mma16816(acc[1 * NT + 2 * p + 1], a1h, bh[2], bh[3]);
            mma16816(acc[0 * NT + 2 * p],     a0h, bl[0], bl[1]);
            mma16816(acc[0 * NT + 2 * p + 1], a0h, bl[2], bl[3]);
            mma16816(acc[1 * NT + 2 * p],     a1h, bl[0], bl[1]);
            mma16816(acc[1 * NT + 2 * p + 1], a1h, bl[2], bl[3]);
            mma16816(acc[0 * NT + 2 * p],     a0l, bh[0], bh[1]);
            mma16816(acc[0 * NT + 2 * p + 1], a0l, bh[2], bh[3]);
            mma16816(acc[1 * NT + 2 * p],     a1l, bh[0], bh[1]);
            mma16816(acc[1 * NT + 2 * p + 1], a1l, bh[2], bh[3]);
        }
    }
}

// cp.async stage of a 256-row x 32-k weight chunk (both splits)
__device__ __forceinline__ void stage_w_cp(unsigned dstHi, unsigned dstLo,
                                           const __nv_bfloat16* wh, const __nv_bfloat16* wl,
                                           int wstr, int kb, int tid)
{
    const int n = tid;
    const char* sh = (const char*)(wh + (size_t)n * wstr + kb);
    const char* sl = (const char*)(wl + (size_t)n * wstr + kb);
#pragma unroll
    for (int j = 0; j < 4; ++j) {
        cp16(dstHi + n * BSTRB + j * 16, sh + j * 16);
        cp16(dstLo + n * BSTRB + j * 16, sl + j * 16);
    }
}
// cp.async stage of a 64-row x 32-k Wq chunk
__device__ __forceinline__ void stage_wq_cp(unsigned dstHi, unsigned dstLo, int kb, int tid)
{
    const int n = tid & 63;
    const int j = tid >> 6;          // 0..3
    cp16(dstHi + n * BSTRB + j * 16, (const char*)(g_Wqt_hi + (size_t)n * HID + kb) + j * 16);
    cp16(dstLo + n * BSTRB + j * 16, (const char*)(g_Wqt_lo + (size_t)n * HID + kb) + j * 16);
}

// X chunk: LDG into regs / split-store into A tile
__device__ __forceinline__ void ldx(const float* __restrict__ X, int m0, int kb, int tid,
                                    float4& x0, float4& x1)
{
    const int row = tid >> 2, kq = (tid & 3) << 3;
    const float* p = X + (size_t)(m0 + row) * F_IN + kb + kq;
    x0 = *(const float4*)p;
    x1 = *(const float4*)(p + 4);
}
__device__ __forceinline__ void stx(char* smem, int tid, float4 x0, float4 x1)
{
    const int row = tid >> 2, kq = (tid & 3) << 3;
    unsigned h[4], l[4];
    split_pack2(x0.x, x0.y, h[0], l[0]); split_pack2(x0.z, x0.w, h[1], l[1]);
    split_pack2(x1.x, x1.y, h[2], l[2]); split_pack2(x1.z, x1.w, h[3], l[3]);
    *(uint4*)(smem + OFF_AS_HI + row * ASTRB + kq * 2) = make_uint4(h[0], h[1], h[2], h[3]);
    *(uint4*)(smem + OFF_AS_LO + row * ASTRB + kq * 2) = make_uint4(l[0], l[1], l[2], l[3]);
}

// epilogue for GEMM1/2: bias + relu + split -> Enc
template<int NT>
__device__ __forceinline__ void epi_relu(float acc[2 * NT][4], const float* __restrict__ bias,
                                         char* smem, int wm, int wnoff, int lane)
{
#pragma unroll
    for (int mi = 0; mi < 2; ++mi)
#pragma unroll
        for (int nj = 0; nj < NT; ++nj) {
            const int r = wm * 32 + mi * 16 + (lane >> 2);
            const int c = wnoff + nj * 8 + 2 * (lane & 3);
            const float bx = bias[c], by = bias[c + 1];
            float* a = acc[mi * NT + nj];
            float x0 = fmaxf(a[0] + bx, 0.f), y0 = fmaxf(a[1] + by, 0.f);
            float x1 = fmaxf(a[2] + bx, 0.f), y1 = fmaxf(a[3] + by, 0.f);
            unsigned h0, l0, h1, l1;
            split_pack2(x0, y0, h0, l0);
            split_pack2(x1, y1, h1, l1);
            *(unsigned*)(smem + OFF_ENC_HI + r * ESTRB + c * 2)       = h0;
            *(unsigned*)(smem + OFF_ENC_LO + r * ESTRB + c * 2)       = l0;
            *(unsigned*)(smem + OFF_ENC_HI + (r + 8) * ESTRB + c * 2) = h1;
            *(unsigned*)(smem + OFF_ENC_LO + (r + 8) * ESTRB + c * 2) = l1;
            a[0] = a[1] = a[2] = a[3] = 0.f;
        }
}

// ---- main fused kernel ----
extern "C" __global__ void __launch_bounds__(THREADS, 1)
uqr_main(const float* __restrict__ X,  const float* __restrict__ b1p,
         const float* __restrict__ b2p, const float* __restrict__ bqp,
         const float* __restrict__ Whp, const float* __restrict__ bhp,
         float* __restrict__ out)
{
    extern __shared__ char smem[];
    const unsigned sb = smem_u32(smem);
    const int tid  = threadIdx.x;
    const int lane = tid & 31;
    const int wid  = tid >> 5;
    const int wm   = wid & 1;          // 2 warp-rows (32 rows each)
    const int wn   = wid >> 1;         // 4 warp-cols
    const int m0   = blockIdx.x * BM;

    const unsigned aHi = sb + OFF_AS_HI, aLo = sb + OFF_AS_LO;
    const unsigned eHi = sb + OFF_ENC_HI, eLo = sb + OFF_ENC_LO;
    const unsigned bufH[2] = { sb + OFF_B0H, sb + OFF_B1H };
    const unsigned bufL[2] = { sb + OFF_B0L, sb + OFF_B1L };

    float acc[16][4];
#pragma unroll
    for (int i = 0; i < 16; ++i)
        acc[i][0] = acc[i][1] = acc[i][2] = acc[i][3] = 0.f;

    // ============== GEMM1: enc1 = relu(X @ W1 + b1), 16 chunks ==============
    float4 x0, x1;
    ldx(X, m0, 0, tid, x0, x1);
    stage_w_cp(bufH[0], bufL[0], g_W1t_hi, g_W1t_lo, F_IN, 0, tid);
    CP_COMMIT();
#pragma unroll 1
    for (int c = 0; c < F_IN / BK; ++c) {
        CP_WAIT0();                              // weight chunk c landed
        stx(smem, tid, x0, x1);                  // X chunk c -> A tile
        __syncthreads();
        if (c + 1 < F_IN / BK) {
            ldx(X, m0, (c + 1) * BK, tid, x0, x1);
            stage_w_cp(bufH[(c + 1) & 1], bufL[(c + 1) & 1],
                       g_W1t_hi, g_W1t_lo, F_IN, (c + 1) * BK, tid);
            CP_COMMIT();
        }
        gemm_chunk<8>(aHi, aLo, ASTRB, 0, bufH[c & 1], bufL[c & 1], wm, wn * 64, lane, acc);
        __syncthreads();                         // A + buf reusable
    }
    stage_w_cp(bufH[0], bufL[0], g_W2t_hi, g_W2t_lo, HID, 0, tid);
    CP_COMMIT();
    epi_relu<8>(acc, b1p, smem, wm, wn * 64, lane);

    // ============== GEMM2: enc2 = relu(enc1 @ W2 + b2), 8 chunks =============
#pragma unroll 1
    for (int c = 0; c < HID / BK; ++c) {
        CP_WAIT0();
        __syncthreads();                         // Enc + weight chunk visible
        if (c + 1 < HID / BK) {
            stage_w_cp(bufH[(c + 1) & 1], bufL[(c + 1) & 1],
                       g_W2t_hi, g_W2t_lo, HID, (c + 1) * BK, tid);
            CP_COMMIT();
        }
        gemm_chunk<8>(eHi, eLo, ESTRB, c * BK, bufH[c & 1], bufL[c & 1], wm, wn * 64, lane, acc);
    }
    __syncthreads();                             // all warps done reading Enc
    stage_wq_cp(bufH[0], bufL[0], 0, tid);
    CP_COMMIT();
    epi_relu<8>(acc, b2p, smem, wm, wn * 64, lane);

    // ============== GEMM3: z3 = enc2 @ Wq + bq (N=64), 8 chunks ==============
#pragma unroll 1
    for (int c = 0; c < HID / BK; ++c) {
        CP_WAIT0();
        __syncthreads();
        if (c + 1 < HID / BK) {
            stage_wq_cp(bufH[(c + 1) & 1], bufL[(c + 1) & 1], (c + 1) * BK, tid);
            CP_COMMIT();
        }
        gemm_chunk<2>(eHi, eLo, ESTRB, c * BK, bufH[c & 1], bufL[c & 1], wm, wn * 16, lane, acc);
    }

    // ===== epilogue 3: tanh + dot(Wh), deterministic reduction =====
    float s = 0.f;
#pragma unroll
    for (int mi = 0; mi < 2; ++mi)
#pragma unroll
        for (int nj = 0; nj < 2; ++nj) {
            const int c = wn * 16 + nj * 8 + 2 * (lane & 3);
            const float bx = bqp[c], by = bqp[c + 1];
            const float wx = Whp[c], wy = Whp[c + 1];
            float* a = acc[mi * 2 + nj];
            s += tanhf(a[0] + bx) * wx + tanhf(a[1] + by) * wy;
            s += tanhf(a[2] + bx) * wx + tanhf(a[3] + by) * wy;
        }
#pragma unroll
    for (int o = 16; o; o >>= 1) s += __shfl_xor_sync(0xffffffffu, s, o);
    float* red = (float*)(smem + OFF_RED);
    if (lane == 0) red[wid] = s;
    __syncthreads();

    if (tid == 0) {
        float t = 0.f;
#pragma unroll
        for (int w = 0; w < 8; ++w) t += red[w];
        g_part[blockIdx.x] = t;
        __threadfence();
        unsigned old = atomicAdd(&g_cnt, 1);
        if (old == NBLK - 1) {            // last CTA: deterministic serial sum
            __threadfence();
            float acc2 = bhp[0];
#pragma unroll 8
            for (int i = 0; i < NBLK; ++i) acc2 += ((volatile float*)g_part)[i];
            out[0] = acc2;
            *((volatile unsigned*)&g_cnt) = 0;   // reset for next replay
        }
    }
}

extern "C" void kernel_launch(void* const* d_in, const int* in_sizes, int n_in,
                              void* d_out, int out_size)
{
    const float* X  = (const float*)d_in[0];
    const float* W1 = (const float*)d_in[1];
    const float* b1 = (const float*)d_in[2];
    const float* W2 = (const float*)d_in[3];
    const float* b2 = (const float*)d_in[4];
    const float* Wq = (const float*)d_in[5];
    const float* bq = (const float*)d_in[6];
    const float* Wh = (const float*)d_in[7];
    const float* bh = (const float*)d_in[8];
    float* out = (float*)d_out;

    const int prep_elems = HID * F_IN + HID * HID + WDIM * HID;
    uqr_prep<<<(prep_elems + 255) / 256, 256>>>(W1, W2, Wq);

    cudaFuncSetAttribute(uqr_main, cudaFuncAttributeMaxDynamicSharedMemorySize, SMEM_TOTAL);
    uqr_main<<<NBLK, THREADS, SMEM_TOTAL>>>(X, b1, b2, bq, Wh, bh, out);
}